// round 9
// baseline (speedup 1.0000x reference)
#include <cuda_runtime.h>
#include <cuda_bf16.h>
#include <math.h>
#include <stdint.h>

#define E_N     100000
#define NODES   10000
#define DIMIN   72
#define NR      1216
#define HID     100
#define NY      25
#define M_PAD   100096          // 782 * 128

// ---------------- scratch (device globals; zero-init) ----------------
__device__ float    g_R [(size_t)E_N * NR];
__device__ float    g_Yb[(size_t)E_N * NY];
__device__ float    g_CG[1225];
__device__ float    g_K [25];
__device__ uint32_t g_planTY[259];
__device__ uint32_t g_planG [552];
__device__ uint32_t g_X1hi[(size_t)M_PAD * 64];
__device__ uint32_t g_X1lo[(size_t)M_PAD * 64];
__device__ uint32_t g_X2hi[(size_t)M_PAD * 64];
__device__ uint32_t g_X2lo[(size_t)M_PAD * 64];
__device__ uint32_t g_X3hi[(size_t)M_PAD * 64];
__device__ uint32_t g_X3lo[(size_t)M_PAD * 64];
__device__ uint32_t g_W1Thi[128 * 64];
__device__ uint32_t g_W1Tlo[128 * 64];
__device__ uint32_t g_W2Thi[128 * 64];
__device__ uint32_t g_W2Tlo[128 * 64];
__device__ uint32_t g_W3Thi[NR * 64];
__device__ uint32_t g_W3Tlo[NR * 64];

// ---------------- triple metadata (19 (lo,li,l) triples) ----------------
__constant__ int TRIP_LO[19]   = {0,0,0, 1,1,1,1,1,1,1, 2,2,2,2,2,2,2,2,2};
__constant__ int TRIP_LI[19]   = {0,1,2, 0,1,1,1,2,2,2, 0,1,1,1,2,2,2,2,2};
__constant__ int TRIP_L [19]   = {0,1,2, 1,0,1,2,1,2,3, 2,1,2,3,0,1,2,3,4};
__constant__ int TRIP_CGO[19]  = {0,1,10, 35,44,53,80,125,170,245, 350,375,420,495,600,625,700,825,1000};
__constant__ int TRIP_RB[19]   = {0,64,128, 192,256,256,256,448,448,448, 640,704,704,704,896,896,896,896,896};
__constant__ int TRIP_FB[19]   = {0,8,32, 0,8,8,8,32,32,32, 0,8,8,8,32,32,32,32,32};
__constant__ int TRIP_KK[19]   = {0,0,0, 0,0,1,2,0,1,2, 0,0,1,2,0,1,2,3,4};
__constant__ int TRIP_NL[19]   = {1,1,1, 1,3,3,3,3,3,3, 1,3,3,3,5,5,5,5,5};
__constant__ int TRIP_NP[19]   = {1,1,1, 3,3,3,3,3,3,3, 5,5,5,5,5,5,5,5,5};
__constant__ int TRIP_NQ[19]   = {1,3,5, 1,3,3,3,5,5,5, 1,3,3,3,5,5,5,5,5};
__constant__ int TY_OFF[20] = {0,1,4,9, 12,21,30,39,54,69, 84,89,104,119,134,159,184,209,234, 259};
__constant__ int G_OFF [20] = {0,8,16, 24,48,72,96,120,144,168, 192,232,272,312,352,392,432,472,512, 552};
__constant__ int TSTART[4] = {0, 3, 10, 19};

__device__ __forceinline__ uint32_t smem_u32(const void* p) {
    uint32_t a;
    asm("{ .reg .u64 t; cvta.to.shared.u64 t, %1; cvt.u32.u64 %0, t; }" : "=r"(a) : "l"(p));
    return a;
}

// ---------------- CG math (doubles) ----------------
__device__ __forceinline__ double dfact(int n) {
    const double f[11] = {1.,1.,2.,6.,24.,120.,720.,5040.,40320.,362880.,3628800.};
    return f[n];
}
__device__ double w3j(int j1,int j2,int j3,int m1,int m2,int m3) {
    if (m1 + m2 + m3 != 0) return 0.0;
    if (j3 < abs(j1 - j2) || j3 > j1 + j2) return 0.0;
    if (abs(m1) > j1 || abs(m2) > j2 || abs(m3) > j3) return 0.0;
    double pre = sqrt(dfact(j1+j2-j3)*dfact(j1-j2+j3)*dfact(-j1+j2+j3)/dfact(j1+j2+j3+1)
                 *dfact(j1+m1)*dfact(j1-m1)*dfact(j2+m2)*dfact(j2-m2)*dfact(j3+m3)*dfact(j3-m3));
    int kmin = max(0, max(j2 - j3 - m1, j1 - j3 + m2));
    int kmax = min(j1 + j2 - j3, min(j1 - m1, j2 + m2));
    double s = 0.0;
    for (int k = kmin; k <= kmax; ++k) {
        double den = dfact(k)*dfact(j1+j2-j3-k)*dfact(j1-m1-k)*dfact(j2+m2-k)
                    *dfact(j3-j2+m1+k)*dfact(j3-j1-m2+k);
        s += ((k & 1) ? -1.0 : 1.0) / den;
    }
    int ph = j1 - j2 - m3;
    return ((ph & 1) ? -1.0 : 1.0) * pre * s;
}
__device__ __forceinline__ double2 Uent(int l, int a, int mc) {
    const double is2 = 0.70710678118654752440;
    int mr = a - l, m = mc - l;
    double2 z; z.x = 0.0; z.y = 0.0;
    if (mr == 0) { if (m == 0) z.x = 1.0; }
    else if (mr > 0) {
        if (m == mr)       z.x = ((mr & 1) ? -1.0 : 1.0) * is2;
        else if (m == -mr) z.x = is2;
    } else {
        int ma = -mr;
        if (m == mr)      z.y = is2;
        else if (m == ma) z.y = -((ma & 1) ? -1.0 : 1.0) * is2;
    }
    return z;
}
__device__ __forceinline__ double2 cmul(double2 a, double2 b) {
    double2 r; r.x = a.x*b.x - a.y*b.y; r.y = a.x*b.y + a.y*b.x; return r;
}

// warp-per-entry CG init; block 0 also fills K norms and plan tables
__global__ void cg_init_kernel() {
    int gw = (blockIdx.x * blockDim.x + threadIdx.x) >> 5;
    int lane = threadIdx.x & 31;

    if (blockIdx.x == 0) {
        for (int t = threadIdx.x; t < 25 + 259 + 552; t += 256) {
            if (t < 25) {
                int c = t;
                int l = 0;
                while ((l+1)*(l+1) <= c) l++;
                int m = c - l*l - l;
                int am = abs(m);
                double K = sqrt((2.0*l + 1.0) / (4.0 * 3.14159265358979323846) * dfact(l - am) / dfact(l + am));
                g_K[c] = (float)(m == 0 ? K : sqrt(2.0) * K);
            } else if (t < 25 + 259) {
                int item = t - 25;
                int tr = 0;
                while (item >= TY_OFF[tr + 1]) ++tr;
                int local = item - TY_OFF[tr];
                int np = TRIP_NP[tr], nq = TRIP_NQ[tr];
                int q = local / np, p = local % np;
                int l = TRIP_L[tr], nr2 = 2 * l + 1;
                uint32_t cgbase = (uint32_t)(TRIP_CGO[tr] + (p * nq + q) * nr2);
                g_planTY[item] = cgbase | ((uint32_t)(l * l) << 12) | ((uint32_t)nr2 << 17);
            } else {
                int item = t - 25 - 259;
                int tr = 0;
                while (item >= G_OFF[tr + 1]) ++tr;
                int local = item - G_OFF[tr];
                int np = TRIP_NP[tr], nq = TRIP_NQ[tr];
                int v = local / np, p = local % np;
                uint32_t fbase = (uint32_t)(TRIP_FB[tr] + v * nq);
                uint32_t tyb   = (uint32_t)(TY_OFF[tr] + p);
                g_planG[item] = fbase | ((uint32_t)nq << 7) | (tyb << 10) | ((uint32_t)np << 19);
            }
        }
    }

    if (gw >= 1225) return;
    int idx = gw;
    int t = 0;
    for (t = 0; t < 19; ++t) {
        int sz = (2*TRIP_LO[t]+1) * (2*TRIP_LI[t]+1) * (2*TRIP_L[t]+1);
        if (idx < TRIP_CGO[t] + sz) break;
    }
    int lo = TRIP_LO[t], li = TRIP_LI[t], l = TRIP_L[t];
    int local = idx - TRIP_CGO[t];
    int nq = 2*li + 1, nr = 2*l + 1;
    int p = local / (nq * nr);
    int q = (local / nr) % nq;
    int r = local % nr;
    int n1 = 2*lo + 1;
    int total = n1 * nq * nr;
    double s = 0.0;
    for (int it = lane; it < total; it += 32) {
        int m  = it / (nq * nr);
        int rem = it % (nq * nr);
        int n  = rem / nr;
        int pp = rem % nr;
        double2 u1 = Uent(lo, p, m);
        if (u1.x == 0.0 && u1.y == 0.0) continue;
        double2 u2 = Uent(li, q, n);
        if (u2.x == 0.0 && u2.y == 0.0) continue;
        double2 u3 = Uent(l, r, pp);
        if (u3.x == 0.0 && u3.y == 0.0) continue;
        double w = w3j(lo, li, l, m - lo, n - li, pp - l);
        if (w == 0.0) continue;
        double2 u = cmul(cmul(u1, u2), u3);
        s += (u.x + u.y) * w;
    }
#pragma unroll
    for (int off = 16; off > 0; off >>= 1)
        s += __shfl_down_sync(0xffffffffu, s, off);
    if (lane == 0) g_CG[idx] = (float)s;
}

// ---------------- zero output ----------------
__global__ void zero_kernel(float* out, int n) {
    int i = blockIdx.x * blockDim.x + threadIdx.x;
    if (i < n) out[i] = 0.0f;
}

// ---------------- all weight transposes + scale + bf16 split, one kernel ----------------
__global__ void wsplit_all_kernel(const float* __restrict__ W1, const float* __restrict__ W2,
                                  const float* __restrict__ W3) {
    int idx = blockIdx.x * blockDim.x + threadIdx.x;
    const float* W;
    uint32_t *Thi, *Tlo;
    int N, lidx;
    if (idx < 128 * 64)            { W = W1; Thi = g_W1Thi; Tlo = g_W1Tlo; N = HID; lidx = idx; }
    else if (idx < 2 * 128 * 64)   { W = W2; Thi = g_W2Thi; Tlo = g_W2Tlo; N = HID; lidx = idx - 128 * 64; }
    else if (idx < 2 * 128 * 64 + NR * 64) { W = W3; Thi = g_W3Thi; Tlo = g_W3Tlo; N = NR; lidx = idx - 2 * 128 * 64; }
    else return;
    int n = lidx >> 6, kp = lidx & 63;
    uint32_t hi = 0, lo = 0;
#pragma unroll
    for (int h = 0; h < 2; ++h) {
        int k = kp * 2 + h;
        float v = (n < N && k < HID) ? W[(size_t)k * N + n] * 0.1f : 0.0f;
        __nv_bfloat16 bh = __float2bfloat16(v);
        float rem = v - __bfloat162float(bh);
        __nv_bfloat16 bl = __float2bfloat16(rem);
        hi |= (uint32_t)__bfloat16_as_ushort(bh) << (16 * h);
        lo |= (uint32_t)__bfloat16_as_ushort(bl) << (16 * h);
    }
    Thi[lidx] = hi;
    Tlo[lidx] = lo;
}

// ---------------- prep: warp per edge ----------------
__global__ __launch_bounds__(256)
void prep_kernel(const float* __restrict__ dist, const float* __restrict__ rel,
                 const float* __restrict__ W0) {
    int e = blockIdx.x * 8 + (threadIdx.x >> 5);
    int lane = threadIdx.x & 31;
    if (e >= E_N) return;

    float d = dist[e];
    const float sigma_inv = 4.5f;
    const float gnorm_inv = 1.0f / 1.423085244900308f;
    float hb[10];
#pragma unroll
    for (int b = 0; b < 10; ++b) {
        float c = 0.7f + (2.5f / 9.0f) * (float)b;
        float tt = (d - c) * sigma_inv;
        hb[b] = expf(-tt * tt) * gnorm_inv;
    }
    const float s0 = 0.31622776601683794f;

#pragma unroll
    for (int rep = 0; rep < 2; ++rep) {
        int j = lane + rep * 32;
        if (j < 50) {
            uint32_t hi = 0, lo = 0;
#pragma unroll
            for (int h = 0; h < 2; ++h) {
                int o = 2 * j + h;
                float s = 0.0f;
#pragma unroll
                for (int b = 0; b < 10; ++b) s += hb[b] * __ldg(&W0[b * HID + o]);
                s *= s0;
                float v = s / (1.0f + expf(-s));
                __nv_bfloat16 bh = __float2bfloat16(v);
                float rem = v - __bfloat162float(bh);
                __nv_bfloat16 bl = __float2bfloat16(rem);
                hi |= (uint32_t)__bfloat16_as_ushort(bh) << (16 * h);
                lo |= (uint32_t)__bfloat16_as_ushort(bl) << (16 * h);
            }
            g_X1hi[(size_t)e * 64 + j] = hi;
            g_X1lo[(size_t)e * 64 + j] = lo;
        }
    }

    if (lane < 25) {
        float vx = rel[e*3+0], vy = rel[e*3+1], vz = rel[e*3+2];
        float r = sqrtf(vx*vx + vy*vy + vz*vz);
        float inv = 1.0f / fmaxf(r, 1e-9f);
        float x = vx * inv, y = vy * inv, z = vz * inv;

        float A[5], B[5];
        A[0] = 1.0f; B[0] = 0.0f;
#pragma unroll
        for (int m = 1; m <= 4; ++m) {
            A[m] = x * A[m-1] - y * B[m-1];
            B[m] = x * B[m-1] + y * A[m-1];
        }
        float p[5][5];
        p[0][0] = 1.0f;
#pragma unroll
        for (int m = 0; m <= 4; ++m) {
            if (m > 0) p[m][m] = -(2.0f * m - 1.0f) * p[m-1][m-1];
            if (m + 1 <= 4) p[m+1][m] = (2.0f * m + 1.0f) * z * p[m][m];
#pragma unroll
            for (int l = m + 2; l <= 4; ++l)
                p[l][m] = ((2.0f*l - 1.0f) * z * p[l-1][m] - (l + m - 1.0f) * p[l-2][m]) / (float)(l - m);
        }
        float val = 0.0f;
        int c = 0;
#pragma unroll
        for (int l = 0; l <= 4; ++l) {
#pragma unroll
            for (int m = -4; m <= 4; ++m) {
                if (m < -l || m > l) continue;
                int am = m < 0 ? -m : m;
                if (c == lane) {
                    float gk = g_K[c];
                    if (m == 0)      val = gk * p[l][0];
                    else if (m > 0)  val = gk * p[l][am] * A[am];
                    else             val = gk * p[l][am] * B[am];
                }
                c++;
            }
        }
        g_Yb[(size_t)e * NY + lane] = val;
    }
}

// ================= mma.sync GEMM machinery (bf16 split, fp32 acc) =================
#define AW     17
#define AHI4   0
#define ALO4   (128 * AW)
#define BHI4   (2 * 128 * AW)
#define BLO4   (2 * 128 * AW + 64 * AW)
#define SM4_TOT (2 * 128 * AW + 2 * 64 * AW)   // 6528 uint4 = 104448 B

__device__ __forceinline__ void ldsm_x4(uint32_t addr, uint32_t& r0, uint32_t& r1, uint32_t& r2, uint32_t& r3) {
    asm volatile("ldmatrix.sync.aligned.m8n8.x4.shared.b16 {%0,%1,%2,%3}, [%4];"
                 : "=r"(r0), "=r"(r1), "=r"(r2), "=r"(r3) : "r"(addr));
}
__device__ __forceinline__ void mma_bf16(float* c, uint32_t a0, uint32_t a1, uint32_t a2, uint32_t a3,
                                         uint32_t b0, uint32_t b1) {
    asm volatile("mma.sync.aligned.m16n8k16.row.col.f32.bf16.bf16.f32 "
                 "{%0,%1,%2,%3}, {%4,%5,%6,%7}, {%8,%9}, {%0,%1,%2,%3};"
                 : "+f"(c[0]), "+f"(c[1]), "+f"(c[2]), "+f"(c[3])
                 : "r"(a0), "r"(a1), "r"(a2), "r"(a3), "r"(b0), "r"(b1));
}

__device__ __forceinline__ void mma_tile_compute(uint32_t smb, uint32_t aoff, uint32_t boff, float acc[8][4]) {
#pragma unroll
    for (int i = 0; i < 8; ++i)
#pragma unroll
        for (int j = 0; j < 4; ++j) acc[i][j] = 0.0f;
#pragma unroll
    for (int seg = 0; seg < 3; ++seg) {
        const uint32_t Ab = smb + (seg == 2 ? ALO4 : AHI4) * 16 + aoff;
        const uint32_t Bb = smb + (seg == 1 ? BLO4 : BHI4) * 16 + boff;
#pragma unroll
        for (int ks = 0; ks < 8; ++ks) {
            uint32_t a0, a1, a2, a3;
            ldsm_x4(Ab + ks * 32, a0, a1, a2, a3);
#pragma unroll
            for (int ncp = 0; ncp < 4; ++ncp) {
                uint32_t b0, b1, b2, b3;
                ldsm_x4(Bb + ncp * (16 * AW * 16) + ks * 32, b0, b1, b2, b3);
                mma_bf16(acc[2 * ncp],     a0, a1, a2, a3, b0, b1);
                mma_bf16(acc[2 * ncp + 1], a0, a1, a2, a3, b2, b3);
            }
        }
    }
}

// MODE 0: store fp32 R streaming (guard rows >= E_N).  MODE 1: silu + bf16 split store.
// __launch_bounds__(256, 2): two CTAs per SM (16 warps) is the whole point — the
// round-8 profile showed 1 CTA/SM (251 regs) left the tensor pipe 83% idle.
template<int NT, int MODE>
__global__ __launch_bounds__(256, 2)
void mma_gemm_kernel(const uint32_t* __restrict__ Ahi, const uint32_t* __restrict__ Alo,
                     const uint32_t* __restrict__ Bhi, const uint32_t* __restrict__ Blo,
                     float* __restrict__ Rout,
                     uint32_t* __restrict__ Chi, uint32_t* __restrict__ Clo) {
    extern __shared__ __align__(16) uint4 sm4[];
    const uint32_t smb = smem_u32(sm4);

    const int tid  = threadIdx.x;
    const int w    = tid >> 5;
    const int lane = tid & 31;
    const int bm   = blockIdx.x * 128;

    {
        const uint4* __restrict__ Ah = (const uint4*)(Ahi + (size_t)bm * 64);
        const uint4* __restrict__ Al = (const uint4*)(Alo + (size_t)bm * 64);
        for (int i = tid; i < 128 * 16; i += 256) {
            int r = i >> 4, c = i & 15;
            sm4[AHI4 + r * AW + c] = Ah[i];
            sm4[ALO4 + r * AW + c] = Al[i];
        }
    }

    const int lrow = lane & 7;
    const int msel = lane >> 3;
    const uint32_t aoff = ((16 * w + lrow + ((msel & 1) << 3)) * AW + (msel >> 1)) * 16;
    const uint32_t boff = ((lrow + ((msel >> 1) << 3)) * AW + (msel & 1)) * 16;

    const int tg  = lane & 3;
    const int gid = lane >> 2;
    const int row0 = bm + 16 * w + gid;

    for (int nt = 0; nt < NT; ++nt) {
        __syncthreads();   // previous tile's ldsm reads done
        {
            const uint4* __restrict__ Bh = (const uint4*)(Bhi + (size_t)nt * 64 * 64);
            const uint4* __restrict__ Bl = (const uint4*)(Blo + (size_t)nt * 64 * 64);
#pragma unroll
            for (int j = 0; j < 4; ++j) {
                int i = tid + j * 256;
                int r = i >> 4, c = i & 15;
                sm4[BHI4 + r * AW + c] = Bh[i];
                sm4[BLO4 + r * AW + c] = Bl[i];
            }
        }
        __syncthreads();

        float acc[8][4];
        mma_tile_compute(smb, aoff, boff, acc);

        const int bn = nt * 64;
        if (MODE == 0) {
#pragma unroll
            for (int nc = 0; nc < 8; ++nc) {
                int col = bn + 8 * nc + 2 * tg;
                if (row0 < E_N)
                    __stcs((float2*)&Rout[(size_t)row0 * NR + col], make_float2(acc[nc][0], acc[nc][1]));
                if (row0 + 8 < E_N)
                    __stcs((float2*)&Rout[(size_t)(row0 + 8) * NR + col], make_float2(acc[nc][2], acc[nc][3]));
            }
        } else {
#pragma unroll
            for (int nc = 0; nc < 8; ++nc) {
                int c = 8 * nc + 2 * tg;
                int jj = (bn + c) >> 1;
#pragma unroll
                for (int half = 0; half < 2; ++half) {
                    int row = row0 + half * 8;
                    uint32_t hi = 0, lo = 0;
#pragma unroll
                    for (int h = 0; h < 2; ++h) {
                        float a = acc[nc][half * 2 + h];
                        float v = a / (1.0f + expf(-a));
                        __nv_bfloat16 bh = __float2bfloat16(v);
                        float rem = v - __bfloat162float(bh);
                        __nv_bfloat16 bl = __float2bfloat16(rem);
                        hi |= (uint32_t)__bfloat16_as_ushort(bh) << (16 * h);
                        lo |= (uint32_t)__bfloat16_as_ushort(bl) << (16 * h);
                    }
                    Chi[(size_t)row * 64 + jj] = hi;
                    Clo[(size_t)row * 64 + jj] = lo;
                }
            }
        }
    }
}

// ---------------- message + scatter: 128 threads per edge, plan tables ----------------
__global__ __launch_bounds__(128)
void msg_kernel(const int* __restrict__ ei, const float* __restrict__ x, float* __restrict__ out) {
    __shared__ float Rs[NR];
    __shared__ float Fs[DIMIN];
    __shared__ float Ys[NY];
    __shared__ float tYs[259];
    __shared__ float Gsm[552];

    const int e = blockIdx.x;
    const int t = threadIdx.x;
    const int src = ei[e];
    const int dst = ei[E_N + e];

    const float4* Rsrc = (const float4*)(g_R + (size_t)e * NR);
    float4* Rd = (float4*)Rs;
    for (int i = t; i < NR / 4; i += 128) Rd[i] = __ldcs(&Rsrc[i]);
    if (t < DIMIN) Fs[t] = x[(size_t)src * DIMIN + t];
    if (t < NY) Ys[t] = g_Yb[(size_t)e * NY + t];
    __syncthreads();

    for (int item = t; item < 259; item += 128) {
        uint32_t plan = __ldg(&g_planTY[item]);
        int cg  = plan & 0xFFF;
        int yb  = (plan >> 12) & 31;
        int nr2 = plan >> 17;
        float s = 0.0f;
        for (int r = 0; r < nr2; ++r)
            s += __ldg(&g_CG[cg + r]) * Ys[yb + r];
        tYs[item] = s;
    }
    __syncthreads();

    for (int item = t; item < 552; item += 128) {
        uint32_t plan = __ldg(&g_planG[item]);
        int fb  = plan & 127;
        int nq  = (plan >> 7) & 7;
        int tyb = (plan >> 10) & 511;
        int np  = (plan >> 19) & 7;
        float s = 0.0f;
        for (int q = 0; q < nq; ++q)
            s += Fs[fb + q] * tYs[tyb + q * np];
        Gsm[item] = s;
    }
    __syncthreads();

    if (t < DIMIN) {
        int o = t;
        int i, u, p, np;
        if (o < 8)       { i = 0; u = o;            p = 0;            np = 1; }
        else if (o < 32) { i = 1; u = (o - 8) / 3;  p = (o - 8) % 3;  np = 3; }
        else             { i = 2; u = (o - 32) / 5; p = (o - 32) % 5; np = 5; }
        float acc = 0.0f;
        for (int tr = TSTART[i]; tr < TSTART[i + 1]; ++tr) {
            int nl = TRIP_NL[tr], kk = TRIP_KK[tr];
            int rb = TRIP_RB[tr] + u * 8 * nl + kk;
            int gb = G_OFF[tr] + p;
            float s = 0.0f;
#pragma unroll
            for (int v = 0; v < 8; ++v)
                s += Rs[rb + v * nl] * Gsm[gb + v * np];
            acc += s;
        }
        const float nse[3] = {24.0f, 56.0f, 72.0f};
        float normi = 3.5449077018110318f * sqrtf(2.0f * i + 1.0f) * rsqrtf(nse[i]);
        atomicAdd(&out[(size_t)dst * DIMIN + o], acc * normi);
    }
}

// ---------------- launch ----------------
extern "C" void kernel_launch(void* const* d_in, const int* in_sizes, int n_in,
                              void* d_out, int out_size) {
    const int*   ei   = (const int*)  d_in[0];
    const float* x    = (const float*)d_in[1];
    const float* dist = (const float*)d_in[2];
    const float* rel  = (const float*)d_in[3];
    const float* W0   = (const float*)d_in[4];
    const float* W1   = (const float*)d_in[5];
    const float* W2   = (const float*)d_in[6];
    const float* W3   = (const float*)d_in[7];
    float* out = (float*)d_out;

    uint32_t *pX1h, *pX1l, *pX2h, *pX2l, *pX3h, *pX3l;
    uint32_t *pW1h, *pW1l, *pW2h, *pW2l, *pW3h, *pW3l;
    float *pR;
    cudaGetSymbolAddress((void**)&pX1h, g_X1hi); cudaGetSymbolAddress((void**)&pX1l, g_X1lo);
    cudaGetSymbolAddress((void**)&pX2h, g_X2hi); cudaGetSymbolAddress((void**)&pX2l, g_X2lo);
    cudaGetSymbolAddress((void**)&pX3h, g_X3hi); cudaGetSymbolAddress((void**)&pX3l, g_X3lo);
    cudaGetSymbolAddress((void**)&pW1h, g_W1Thi); cudaGetSymbolAddress((void**)&pW1l, g_W1Tlo);
    cudaGetSymbolAddress((void**)&pW2h, g_W2Thi); cudaGetSymbolAddress((void**)&pW2l, g_W2Tlo);
    cudaGetSymbolAddress((void**)&pW3h, g_W3Thi); cudaGetSymbolAddress((void**)&pW3l, g_W3Tlo);
    cudaGetSymbolAddress((void**)&pR,  g_R);

    cudaFuncSetAttribute(mma_gemm_kernel<2, 1>, cudaFuncAttributeMaxDynamicSharedMemorySize, SM4_TOT * 16);
    cudaFuncSetAttribute(mma_gemm_kernel<19, 0>, cudaFuncAttributeMaxDynamicSharedMemorySize, SM4_TOT * 16);

    const int grid = M_PAD / 128;   // 782

    cg_init_kernel<<<154, 256>>>();                                                  // 1
    wsplit_all_kernel<<<((2 * 128 + NR) * 64 + 255) / 256, 256>>>(W1, W2, W3);       // 2
    prep_kernel<<<(E_N + 7) / 8, 256>>>(dist, rel, W0);                              // 3
    mma_gemm_kernel<2, 1><<<grid, 256, SM4_TOT * 16>>>(pX1h, pX1l, pW1h, pW1l, nullptr, pX2h, pX2l); // 4
    mma_gemm_kernel<2, 1><<<grid, 256, SM4_TOT * 16>>>(pX2h, pX2l, pW2h, pW2l, nullptr, pX3h, pX3l); // 5
    mma_gemm_kernel<19, 0><<<grid, 256, SM4_TOT * 16>>>(pX3h, pX3l, pW3h, pW3l, pR, nullptr, nullptr); // 6
    zero_kernel<<<(out_size + 255) / 256, 256>>>(out, out_size);                     // 7
    msg_kernel<<<E_N, 128>>>(ei, x, out);                                            // 8
}

// round 10
// speedup vs baseline: 2.2288x; 2.2288x over previous
#include <cuda_runtime.h>
#include <math.h>
#include <stdint.h>

#define E_N     100000
#define NODES   10000
#define DIMIN   72
#define NR      1216
#define HID     100
#define NY      25
#define NT_TAB  513            // radial table nodes over [0.7, 3.2], h = 2.5/512

// ---------------- scratch (device globals; zero-init) ----------------
__device__ float    g_T [(size_t)NT_TAB * NR];   // radial table f(d_j)
__device__ float    g_Yb[(size_t)E_N * NY];
__device__ float    g_CG[1225];
__device__ float    g_K [25];
__device__ uint32_t g_planTY[259];
__device__ uint32_t g_planG [552];

// ---------------- triple metadata (19 (lo,li,l) triples) ----------------
__constant__ int TRIP_LO[19]   = {0,0,0, 1,1,1,1,1,1,1, 2,2,2,2,2,2,2,2,2};
__constant__ int TRIP_LI[19]   = {0,1,2, 0,1,1,1,2,2,2, 0,1,1,1,2,2,2,2,2};
__constant__ int TRIP_L [19]   = {0,1,2, 1,0,1,2,1,2,3, 2,1,2,3,0,1,2,3,4};
__constant__ int TRIP_CGO[19]  = {0,1,10, 35,44,53,80,125,170,245, 350,375,420,495,600,625,700,825,1000};
__constant__ int TRIP_RB[19]   = {0,64,128, 192,256,256,256,448,448,448, 640,704,704,704,896,896,896,896,896};
__constant__ int TRIP_FB[19]   = {0,8,32, 0,8,8,8,32,32,32, 0,8,8,8,32,32,32,32,32};
__constant__ int TRIP_KK[19]   = {0,0,0, 0,0,1,2,0,1,2, 0,0,1,2,0,1,2,3,4};
__constant__ int TRIP_NL[19]   = {1,1,1, 1,3,3,3,3,3,3, 1,3,3,3,5,5,5,5,5};
__constant__ int TRIP_NP[19]   = {1,1,1, 3,3,3,3,3,3,3, 5,5,5,5,5,5,5,5,5};
__constant__ int TRIP_NQ[19]   = {1,3,5, 1,3,3,3,5,5,5, 1,3,3,3,5,5,5,5,5};
__constant__ int TY_OFF[20] = {0,1,4,9, 12,21,30,39,54,69, 84,89,104,119,134,159,184,209,234, 259};
__constant__ int G_OFF [20] = {0,8,16, 24,48,72,96,120,144,168, 192,232,272,312,352,392,432,472,512, 552};
__constant__ int TSTART[4] = {0, 3, 10, 19};

// ---------------- CG math (doubles) ----------------
__device__ __forceinline__ double dfact(int n) {
    const double f[11] = {1.,1.,2.,6.,24.,120.,720.,5040.,40320.,362880.,3628800.};
    return f[n];
}
__device__ double w3j(int j1,int j2,int j3,int m1,int m2,int m3) {
    if (m1 + m2 + m3 != 0) return 0.0;
    if (j3 < abs(j1 - j2) || j3 > j1 + j2) return 0.0;
    if (abs(m1) > j1 || abs(m2) > j2 || abs(m3) > j3) return 0.0;
    double pre = sqrt(dfact(j1+j2-j3)*dfact(j1-j2+j3)*dfact(-j1+j2+j3)/dfact(j1+j2+j3+1)
                 *dfact(j1+m1)*dfact(j1-m1)*dfact(j2+m2)*dfact(j2-m2)*dfact(j3+m3)*dfact(j3-m3));
    int kmin = max(0, max(j2 - j3 - m1, j1 - j3 + m2));
    int kmax = min(j1 + j2 - j3, min(j1 - m1, j2 + m2));
    double s = 0.0;
    for (int k = kmin; k <= kmax; ++k) {
        double den = dfact(k)*dfact(j1+j2-j3-k)*dfact(j1-m1-k)*dfact(j2+m2-k)
                    *dfact(j3-j2+m1+k)*dfact(j3-j1-m2+k);
        s += ((k & 1) ? -1.0 : 1.0) / den;
    }
    int ph = j1 - j2 - m3;
    return ((ph & 1) ? -1.0 : 1.0) * pre * s;
}
__device__ __forceinline__ double2 Uent(int l, int a, int mc) {
    const double is2 = 0.70710678118654752440;
    int mr = a - l, m = mc - l;
    double2 z; z.x = 0.0; z.y = 0.0;
    if (mr == 0) { if (m == 0) z.x = 1.0; }
    else if (mr > 0) {
        if (m == mr)       z.x = ((mr & 1) ? -1.0 : 1.0) * is2;
        else if (m == -mr) z.x = is2;
    } else {
        int ma = -mr;
        if (m == mr)      z.y = is2;
        else if (m == ma) z.y = -((ma & 1) ? -1.0 : 1.0) * is2;
    }
    return z;
}
__device__ __forceinline__ double2 cmul(double2 a, double2 b) {
    double2 r; r.x = a.x*b.x - a.y*b.y; r.y = a.x*b.y + a.y*b.x; return r;
}

// warp-per-entry CG init; block 0 also fills K norms and plan tables
__global__ void cg_init_kernel() {
    int gw = (blockIdx.x * blockDim.x + threadIdx.x) >> 5;
    int lane = threadIdx.x & 31;

    if (blockIdx.x == 0) {
        for (int t = threadIdx.x; t < 25 + 259 + 552; t += 256) {
            if (t < 25) {
                int c = t;
                int l = 0;
                while ((l+1)*(l+1) <= c) l++;
                int m = c - l*l - l;
                int am = abs(m);
                double K = sqrt((2.0*l + 1.0) / (4.0 * 3.14159265358979323846) * dfact(l - am) / dfact(l + am));
                g_K[c] = (float)(m == 0 ? K : sqrt(2.0) * K);
            } else if (t < 25 + 259) {
                int item = t - 25;
                int tr = 0;
                while (item >= TY_OFF[tr + 1]) ++tr;
                int local = item - TY_OFF[tr];
                int np = TRIP_NP[tr], nq = TRIP_NQ[tr];
                int q = local / np, p = local % np;
                int l = TRIP_L[tr], nr2 = 2 * l + 1;
                uint32_t cgbase = (uint32_t)(TRIP_CGO[tr] + (p * nq + q) * nr2);
                g_planTY[item] = cgbase | ((uint32_t)(l * l) << 12) | ((uint32_t)nr2 << 17);
            } else {
                int item = t - 25 - 259;
                int tr = 0;
                while (item >= G_OFF[tr + 1]) ++tr;
                int local = item - G_OFF[tr];
                int np = TRIP_NP[tr], nq = TRIP_NQ[tr];
                int v = local / np, p = local % np;
                uint32_t fbase = (uint32_t)(TRIP_FB[tr] + v * nq);
                uint32_t tyb   = (uint32_t)(TY_OFF[tr] + p);
                g_planG[item] = fbase | ((uint32_t)nq << 7) | (tyb << 10) | ((uint32_t)np << 19);
            }
        }
    }

    if (gw >= 1225) return;
    int idx = gw;
    int t = 0;
    for (t = 0; t < 19; ++t) {
        int sz = (2*TRIP_LO[t]+1) * (2*TRIP_LI[t]+1) * (2*TRIP_L[t]+1);
        if (idx < TRIP_CGO[t] + sz) break;
    }
    int lo = TRIP_LO[t], li = TRIP_LI[t], l = TRIP_L[t];
    int local = idx - TRIP_CGO[t];
    int nq = 2*li + 1, nr = 2*l + 1;
    int p = local / (nq * nr);
    int q = (local / nr) % nq;
    int r = local % nr;
    int n1 = 2*lo + 1;
    int total = n1 * nq * nr;
    double s = 0.0;
    for (int it = lane; it < total; it += 32) {
        int m  = it / (nq * nr);
        int rem = it % (nq * nr);
        int n  = rem / nr;
        int pp = rem % nr;
        double2 u1 = Uent(lo, p, m);
        if (u1.x == 0.0 && u1.y == 0.0) continue;
        double2 u2 = Uent(li, q, n);
        if (u2.x == 0.0 && u2.y == 0.0) continue;
        double2 u3 = Uent(l, r, pp);
        if (u3.x == 0.0 && u3.y == 0.0) continue;
        double w = w3j(lo, li, l, m - lo, n - li, pp - l);
        if (w == 0.0) continue;
        double2 u = cmul(cmul(u1, u2), u3);
        s += (u.x + u.y) * w;
    }
#pragma unroll
    for (int off = 16; off > 0; off >>= 1)
        s += __shfl_down_sync(0xffffffffu, s, off);
    if (lane == 0) g_CG[idx] = (float)s;
}

// ---------------- radial table: one block per node, exact fp32 MLP ----------------
__global__ __launch_bounds__(256)
void table_kernel(const float* __restrict__ W0, const float* __restrict__ W1,
                  const float* __restrict__ W2, const float* __restrict__ W3) {
    __shared__ float ha[HID], hbuf[HID], hb[10];
    const int node = blockIdx.x;
    const int t = threadIdx.x;
    const float d = 0.7f + 2.5f * (float)node / (float)(NT_TAB - 1);

    if (t < 10) {
        float c = 0.7f + (2.5f / 9.0f) * (float)t;
        float tt = (d - c) * 4.5f;
        hb[t] = expf(-tt * tt) * (1.0f / 1.423085244900308f);
    }
    __syncthreads();
    if (t < HID) {
        float s = 0.0f;
#pragma unroll
        for (int b = 0; b < 10; ++b) s += hb[b] * W0[b * HID + t];
        s *= 0.31622776601683794f;
        ha[t] = s / (1.0f + expf(-s));
    }
    __syncthreads();
    if (t < HID) {
        float s = 0.0f;
        for (int k = 0; k < HID; ++k) s += ha[k] * W1[k * HID + t];
        s *= 0.1f;
        hbuf[t] = s / (1.0f + expf(-s));
    }
    __syncthreads();
    if (t < HID) {
        float s = 0.0f;
        for (int k = 0; k < HID; ++k) s += hbuf[k] * W2[k * HID + t];
        s *= 0.1f;
        ha[t] = s / (1.0f + expf(-s));
    }
    __syncthreads();
    for (int o = t; o < NR; o += 256) {
        float s = 0.0f;
        for (int k = 0; k < HID; ++k) s += ha[k] * W3[(size_t)k * NR + o];
        g_T[(size_t)node * NR + o] = 0.1f * s;
    }
}

// ---------------- prep: spherical harmonics only (warp per edge) ----------------
__global__ __launch_bounds__(256)
void prep_kernel(const float* __restrict__ rel) {
    int e = blockIdx.x * 8 + (threadIdx.x >> 5);
    int lane = threadIdx.x & 31;
    if (e >= E_N || lane >= 25) return;

    float vx = rel[e*3+0], vy = rel[e*3+1], vz = rel[e*3+2];
    float r = sqrtf(vx*vx + vy*vy + vz*vz);
    float inv = 1.0f / fmaxf(r, 1e-9f);
    float x = vx * inv, y = vy * inv, z = vz * inv;

    float A[5], B[5];
    A[0] = 1.0f; B[0] = 0.0f;
#pragma unroll
    for (int m = 1; m <= 4; ++m) {
        A[m] = x * A[m-1] - y * B[m-1];
        B[m] = x * B[m-1] + y * A[m-1];
    }
    float p[5][5];
    p[0][0] = 1.0f;
#pragma unroll
    for (int m = 0; m <= 4; ++m) {
        if (m > 0) p[m][m] = -(2.0f * m - 1.0f) * p[m-1][m-1];
        if (m + 1 <= 4) p[m+1][m] = (2.0f * m + 1.0f) * z * p[m][m];
#pragma unroll
        for (int l = m + 2; l <= 4; ++l)
            p[l][m] = ((2.0f*l - 1.0f) * z * p[l-1][m] - (l + m - 1.0f) * p[l-2][m]) / (float)(l - m);
    }
    float val = 0.0f;
    int c = 0;
#pragma unroll
    for (int l = 0; l <= 4; ++l) {
#pragma unroll
        for (int m = -4; m <= 4; ++m) {
            if (m < -l || m > l) continue;
            int am = m < 0 ? -m : m;
            if (c == lane) {
                float gk = g_K[c];
                if (m == 0)      val = gk * p[l][0];
                else if (m > 0)  val = gk * p[l][am] * A[am];
                else             val = gk * p[l][am] * B[am];
            }
            c++;
        }
    }
    g_Yb[(size_t)e * NY + lane] = val;
}

// ---------------- zero output (range) ----------------
__global__ void zero_kernel(float* out, int base, int n) {
    int i = base + blockIdx.x * blockDim.x + threadIdx.x;
    if (i < base + n) out[i] = 0.0f;
}

// ---------------- message: cubic-interp R from table + contraction + scatter ----------------
__global__ __launch_bounds__(128)
void msg_kernel(const int* __restrict__ ei, const float* __restrict__ x,
                const float* __restrict__ dist, float* __restrict__ out) {
    __shared__ float Rs[NR];
    __shared__ float Fs[DIMIN];
    __shared__ float Ys[NY];
    __shared__ float tYs[259];
    __shared__ float Gsm[552];

    const int e = blockIdx.x;
    const int t = threadIdx.x;
    const int src = ei[e];
    const int dst = ei[E_N + e];

    // cubic Lagrange interpolation of the radial table
    {
        float u = (dist[e] - 0.7f) * ((float)(NT_TAB - 1) / 2.5f);
        int i0 = (int)floorf(u);
        i0 = min(max(i0, 1), NT_TAB - 3);
        float tt = u - (float)i0;
        float tm = tt - 1.0f, tp = tt + 1.0f, tm2 = tt - 2.0f;
        float w0 = -tt * tm * tm2 * (1.0f / 6.0f);
        float w1 =  tp * tm * tm2 * 0.5f;
        float w2 = -tp * tt * tm2 * 0.5f;
        float w3 =  tp * tt * tm  * (1.0f / 6.0f);
        const float* __restrict__ T0 = g_T + (size_t)(i0 - 1) * NR;
        const float* __restrict__ T1 = T0 + NR;
        const float* __restrict__ T2 = T1 + NR;
        const float* __restrict__ T3 = T2 + NR;
        for (int i = t; i < NR; i += 128)
            Rs[i] = w0 * __ldg(T0 + i) + w1 * __ldg(T1 + i)
                  + w2 * __ldg(T2 + i) + w3 * __ldg(T3 + i);
    }
    if (t < DIMIN) Fs[t] = x[(size_t)src * DIMIN + t];
    if (t < NY) Ys[t] = g_Yb[(size_t)e * NY + t];
    __syncthreads();

    // pass 1: tY
    for (int item = t; item < 259; item += 128) {
        uint32_t plan = __ldg(&g_planTY[item]);
        int cg  = plan & 0xFFF;
        int yb  = (plan >> 12) & 31;
        int nr2 = plan >> 17;
        float s = 0.0f;
        for (int r = 0; r < nr2; ++r)
            s += __ldg(&g_CG[cg + r]) * Ys[yb + r];
        tYs[item] = s;
    }
    __syncthreads();

    // pass 2: G
    for (int item = t; item < 552; item += 128) {
        uint32_t plan = __ldg(&g_planG[item]);
        int fb  = plan & 127;
        int nq  = (plan >> 7) & 7;
        int tyb = (plan >> 10) & 511;
        int np  = (plan >> 19) & 7;
        float s = 0.0f;
        for (int q = 0; q < nq; ++q)
            s += Fs[fb + q] * tYs[tyb + q * np];
        Gsm[item] = s;
    }
    __syncthreads();

    // pass 3: contract with R, scatter
    if (t < DIMIN) {
        int o = t;
        int i, u, p, np;
        if (o < 8)       { i = 0; u = o;            p = 0;            np = 1; }
        else if (o < 32) { i = 1; u = (o - 8) / 3;  p = (o - 8) % 3;  np = 3; }
        else             { i = 2; u = (o - 32) / 5; p = (o - 32) % 5; np = 5; }
        float acc = 0.0f;
        for (int tr = TSTART[i]; tr < TSTART[i + 1]; ++tr) {
            int nl = TRIP_NL[tr], kk = TRIP_KK[tr];
            int rb = TRIP_RB[tr] + u * 8 * nl + kk;
            int gb = G_OFF[tr] + p;
            float s = 0.0f;
#pragma unroll
            for (int v = 0; v < 8; ++v)
                s += Rs[rb + v * nl] * Gsm[gb + v * np];
            acc += s;
        }
        const float nse[3] = {24.0f, 56.0f, 72.0f};
        float normi = 3.5449077018110318f * sqrtf(2.0f * i + 1.0f) * rsqrtf(nse[i]);
        atomicAdd(&out[(size_t)dst * DIMIN + o], acc * normi);
    }
}

// ---------------- launch ----------------
extern "C" void kernel_launch(void* const* d_in, const int* in_sizes, int n_in,
                              void* d_out, int out_size) {
    const int*   ei   = (const int*)  d_in[0];
    const float* x    = (const float*)d_in[1];
    const float* dist = (const float*)d_in[2];
    const float* rel  = (const float*)d_in[3];
    const float* W0   = (const float*)d_in[4];
    const float* W1   = (const float*)d_in[5];
    const float* W2   = (const float*)d_in[6];
    const float* W3   = (const float*)d_in[7];
    float* out = (float*)d_out;

    const int half = out_size / 2;

    // launch order arranged so the 6th launch (ncu -s 5 -c 1) is msg_kernel
    cg_init_kernel<<<154, 256>>>();                                   // 1
    table_kernel<<<NT_TAB, 256>>>(W0, W1, W2, W3);                    // 2
    prep_kernel<<<(E_N + 7) / 8, 256>>>(rel);                         // 3
    zero_kernel<<<(half + 255) / 256, 256>>>(out, 0, half);           // 4
    zero_kernel<<<(out_size - half + 255) / 256, 256>>>(out, half, out_size - half); // 5
    msg_kernel<<<E_N, 128>>>(ei, x, dist, out);                       // 6 <- ncu
}